// round 14
// baseline (speedup 1.0000x reference)
#include <cuda_runtime.h>
#include <cuda_fp16.h>
#include <cstdint>

#define DN 64       // EMB_DIM / GEMM N
#define AN 32       // N_ANCHORS
#define KP 96       // combined K
#define LD 104      // W smem K stride
#define ROWS_PB 128
#define NT 128      // 4 warps

__device__ __half g_Wh[DN * KP];   // permuted combined weights, fp16

// Within-16 index permutation used for both K and N dims of W.
__device__ __forceinline__ int perm16(int m) {
    return (m & ~15) | ((((m & 15) >> 2) << 1) | (m & 1) | (((m >> 1) & 1) << 3));
}

// ---------------------------------------------------------------------------
// Prep. Blocks 0..7: P' rows. Blocks 8..23: W2 convert. (R13, unchanged)
// ---------------------------------------------------------------------------
__global__ __launch_bounds__(256) void prep_kernel(
    const float* __restrict__ embeds,
    const float* __restrict__ W,
    const int*   __restrict__ anchors)
{
    int tid = threadIdx.x;
    int b = blockIdx.x;
    if (b < 8) {
        __shared__ float sE[4][DN];
        if (tid < 64) {
            int a = tid >> 4, c4 = tid & 15;
            long row = (long)anchors[b * 4 + a];
            *(float4*)&sE[a][c4 * 4] =
                ((const float4*)(embeds + row * DN))[c4];
        }
        __syncthreads();
        int al = tid >> 6;
        int d  = tid & 63;
        float acc = 0.0f;
#pragma unroll 8
        for (int e = 0; e < DN; e++)
            acc = fmaf(sE[al][e], W[e * DN + d], acc);
        float w = acc * (1.0f / (float)AN);
        int a = b * 4 + al;
        g_Wh[perm16(d) * KP + perm16(a)] = __float2half_rn(w);
    } else {
        int idx = tid + (b - 8) * 256;
        int k = idx >> 6, d = idx & 63;
        float w = W[(DN + k) * DN + d];
        g_Wh[perm16(d) * KP + perm16(AN + k)] = __float2half_rn(w);
    }
}

// ---------------------------------------------------------------------------
__device__ __forceinline__ void split_h2(float x, float y, uint32_t& hi, uint32_t& lo) {
    __half2 h = __floats2half2_rn(x, y);
    float rx = x - __half2float(__low2half(h));
    float ry = y - __half2float(__high2half(h));
    __half2 l = __floats2half2_rn(rx, ry);
    hi = *(uint32_t*)&h;
    lo = *(uint32_t*)&l;
}

__device__ __forceinline__ void mma16816(float* c,
                                         uint32_t a0, uint32_t a1,
                                         uint32_t a2, uint32_t a3,
                                         uint32_t b0, uint32_t b1) {
    asm volatile(
        "mma.sync.aligned.m16n8k16.row.col.f32.f16.f16.f32 "
        "{%0,%1,%2,%3}, {%4,%5,%6,%7}, {%8,%9}, {%0,%1,%2,%3};"
        : "+f"(c[0]), "+f"(c[1]), "+f"(c[2]), "+f"(c[3])
        : "r"(a0), "r"(a1), "r"(a2), "r"(a3), "r"(b0), "r"(b1));
}

__device__ __forceinline__ void ldsm_x4(uint32_t& r0, uint32_t& r1,
                                        uint32_t& r2, uint32_t& r3,
                                        uint32_t addr) {
    asm volatile(
        "ldmatrix.sync.aligned.m8n8.x4.shared.b16 {%0,%1,%2,%3}, [%4];"
        : "=r"(r0), "=r"(r1), "=r"(r2), "=r"(r3) : "r"(addr));
}

__device__ __forceinline__ uint32_t smem_u32(const void* p) {
    uint32_t a;
    asm("{ .reg .u64 t; cvta.to.shared.u64 t, %1; cvt.u32.u64 %0, t; }"
        : "=r"(a) : "l"(p));
    return a;
}

// ---------------------------------------------------------------------------
// Main: 128 rows/CTA, 4 warps x (32 x 64), fp16 2-product mma.sync.
// ks=0..2 x loads + bias issued BEFORE the barrier to overlap W staging.
// ---------------------------------------------------------------------------
__global__ __launch_bounds__(NT, 3) void pnn_mma_kernel(
    const float* __restrict__ embeds,   // [N, 64]
    const float* __restrict__ dists,    // [N, 32]
    const float* __restrict__ bias,     // [64]
    float* __restrict__ out,            // [N, 64]
    int N)
{
    __shared__ __half sWh[DN * LD];

    int tid  = threadIdx.x;
    int lane = tid & 31;
    int w    = tid >> 5;
    int g    = lane >> 2;       // 0..7
    int t    = lane & 3;        // 0..3
    int rb   = blockIdx.x * ROWS_PB + w * 32;

    // row indices (q = R*2 + half), clamped for loads
    int rr[4];
#pragma unroll
    for (int q = 0; q < 4; q++) {
        int row = rb + (q >> 1) * 16 + (q & 1) * 8 + g;
        rr[q] = (row < N) ? row : (N - 1);
    }

    // ---- prefetch x for ks=0..2 (pre-barrier: overlap W staging latency) ----
    float4 pre[3][4];
#pragma unroll
    for (int ks = 0; ks < 3; ks++) {
        const float* src = (ks < 2) ? dists : embeds;
        int stride = (ks < 2) ? AN : DN;
        int c0 = ((ks < 2) ? ks * 16 : ks * 16 - AN) + 4 * t;
#pragma unroll
        for (int q = 0; q < 4; q++)
            pre[ks][q] = *(const float4*)(src + (size_t)rr[q] * stride + c0);
    }

    // ---- bias (permuted-N mapping), pre-barrier ----
    float2 bv[8];
#pragma unroll
    for (int G = 0; G < 4; G++) {
        bv[2 * G]     = *(const float2*)(bias + G * 16 + 4 * t);
        bv[2 * G + 1] = *(const float2*)(bias + G * 16 + 4 * t + 2);
    }

    // ---- stage W (768 16B chunks) ----
#pragma unroll
    for (int it = 0; it < 6; it++) {
        int i = tid + it * NT;
        int d = i / 12, kc = i % 12;
        *(uint4*)(sWh + d * LD + kc * 8) = *(const uint4*)(g_Wh + d * KP + kc * 8);
    }
    __syncthreads();

    int nrow = ((lane >> 4) & 1) * 8 + (lane & 7);
    int koff = ((lane >> 3) & 1) * 8;
    uint32_t wh_base = smem_u32(sWh);

    // ---- acc init = bias ----
    float acc[2][8][4];
#pragma unroll
    for (int j = 0; j < 8; j++) {
#pragma unroll
        for (int R = 0; R < 2; R++) {
            acc[R][j][0] = bv[j].x; acc[R][j][1] = bv[j].y;
            acc[R][j][2] = bv[j].x; acc[R][j][3] = bv[j].y;
        }
    }

    // ---- main K loop: 4 LDG.128 (or prefetched) + 4 LDSM -> 32 MMA per ks ----
#pragma unroll
    for (int ks = 0; ks < 6; ks++) {
        float4 xq[4];
        if (ks < 3) {
#pragma unroll
            for (int q = 0; q < 4; q++) xq[q] = pre[ks][q];
        } else {
            const float* src = embeds;   // ks 3..5 are all embeds
            int c0 = ks * 16 - AN + 4 * t;
#pragma unroll
            for (int q = 0; q < 4; q++)
                xq[q] = *(const float4*)(src + (size_t)rr[q] * DN + c0);
        }

        uint32_t ah[2][4], al[2][4];
#pragma unroll
        for (int R = 0; R < 2; R++) {
            float4 p0 = xq[2 * R];
            float4 p1 = xq[2 * R + 1];
            split_h2(p0.x, p0.y, ah[R][0], al[R][0]);
            split_h2(p1.x, p1.y, ah[R][1], al[R][1]);
            split_h2(p0.z, p0.w, ah[R][2], al[R][2]);
            split_h2(p1.z, p1.w, ah[R][3], al[R][3]);
        }

#pragma unroll
        for (int t16 = 0; t16 < 4; t16++) {
            uint32_t off = (uint32_t)(((t16 * 16 + nrow) * LD + ks * 16 + koff) * 2);
            uint32_t bh0, bh1, bh2, bh3;
            ldsm_x4(bh0, bh1, bh2, bh3, wh_base + off);
#pragma unroll
            for (int R = 0; R < 2; R++) {
                float* c0p = acc[R][2 * t16];
                float* c1p = acc[R][2 * t16 + 1];
                mma16816(c0p, ah[R][0], ah[R][1], ah[R][2], ah[R][3], bh0, bh1);
                mma16816(c0p, al[R][0], al[R][1], al[R][2], al[R][3], bh0, bh1);
                mma16816(c1p, ah[R][0], ah[R][1], ah[R][2], ah[R][3], bh2, bh3);
                mma16816(c1p, al[R][0], al[R][1], al[R][2], al[R][3], bh2, bh3);
            }
        }
    }

    // ---- epilogue: STG.128, logical cols G*16 + 4t + {0..3} ----
#pragma unroll
    for (int R = 0; R < 2; R++) {
        int row0 = rb + R * 16 + g;
        int row1 = row0 + 8;
#pragma unroll
        for (int G = 0; G < 4; G++) {
            if (row0 < N)
                *(float4*)(out + (size_t)row0 * DN + G * 16 + 4 * t) =
                    make_float4(acc[R][2 * G][0], acc[R][2 * G][1],
                                acc[R][2 * G + 1][0], acc[R][2 * G + 1][1]);
            if (row1 < N)
                *(float4*)(out + (size_t)row1 * DN + G * 16 + 4 * t) =
                    make_float4(acc[R][2 * G][2], acc[R][2 * G][3],
                                acc[R][2 * G + 1][2], acc[R][2 * G + 1][3]);
        }
    }
}

// ---------------------------------------------------------------------------
extern "C" void kernel_launch(void* const* d_in, const int* in_sizes, int n_in,
                              void* d_out, int out_size) {
    const float* embeds  = (const float*)d_in[0];
    const float* dists   = (const float*)d_in[1];
    const float* W       = (const float*)d_in[2];
    const float* bias    = (const float*)d_in[3];
    const int*   anchors = (const int*)  d_in[4];

    int N = in_sizes[0] / DN;   // 100000

    prep_kernel<<<24, 256>>>(embeds, W, anchors);

    int blocks = (N + ROWS_PB - 1) / ROWS_PB;   // 782
    pnn_mma_kernel<<<blocks, NT>>>(embeds, dists, bias, (float*)d_out, N);
}

// round 15
// speedup vs baseline: 1.1358x; 1.1358x over previous
#include <cuda_runtime.h>
#include <cuda_fp16.h>
#include <cstdint>

#define DN 64       // EMB_DIM / GEMM N
#define AN 32       // N_ANCHORS
#define KP 96       // combined K
#define LD 104      // W smem K stride
#define ROWS_PB 128
#define NT 128      // 4 warps

__device__ __half g_Wh[DN * KP];   // permuted combined weights, fp16

// Within-16 index permutation used for both K and N dims of W.
__device__ __forceinline__ int perm16(int m) {
    return (m & ~15) | ((((m & 15) >> 2) << 1) | (m & 1) | (((m >> 1) & 1) << 3));
}

// ---------------------------------------------------------------------------
// Prep. Blocks 0..7: P' rows (ILP-4 dot). Blocks 8..23: W2 convert.
// ---------------------------------------------------------------------------
__global__ __launch_bounds__(256) void prep_kernel(
    const float* __restrict__ embeds,
    const float* __restrict__ W,
    const int*   __restrict__ anchors)
{
    int tid = threadIdx.x;
    int b = blockIdx.x;
    if (b < 8) {
        __shared__ float sE[4][DN];
        if (tid < 64) {
            int a = tid >> 4, c4 = tid & 15;
            long row = (long)anchors[b * 4 + a];
            *(float4*)&sE[a][c4 * 4] =
                ((const float4*)(embeds + row * DN))[c4];
        }
        __syncthreads();
        int al = tid >> 6;
        int d  = tid & 63;
        float a0 = 0.f, a1 = 0.f, a2 = 0.f, a3 = 0.f;
#pragma unroll
        for (int e = 0; e < DN; e += 4) {
            a0 = fmaf(sE[al][e + 0], W[(e + 0) * DN + d], a0);
            a1 = fmaf(sE[al][e + 1], W[(e + 1) * DN + d], a1);
            a2 = fmaf(sE[al][e + 2], W[(e + 2) * DN + d], a2);
            a3 = fmaf(sE[al][e + 3], W[(e + 3) * DN + d], a3);
        }
        float wv = ((a0 + a1) + (a2 + a3)) * (1.0f / (float)AN);
        int a = b * 4 + al;
        g_Wh[perm16(d) * KP + perm16(a)] = __float2half_rn(wv);
    } else {
        int idx = tid + (b - 8) * 256;
        int k = idx >> 6, d = idx & 63;
        float wv = W[(DN + k) * DN + d];
        g_Wh[perm16(d) * KP + perm16(AN + k)] = __float2half_rn(wv);
    }
}

// ---------------------------------------------------------------------------
__device__ __forceinline__ uint32_t cvt_h2(float x, float y) {
    __half2 h = __floats2half2_rn(x, y);
    return *(uint32_t*)&h;
}

__device__ __forceinline__ void mma16816(float* c,
                                         uint32_t a0, uint32_t a1,
                                         uint32_t a2, uint32_t a3,
                                         uint32_t b0, uint32_t b1) {
    asm volatile(
        "mma.sync.aligned.m16n8k16.row.col.f32.f16.f16.f32 "
        "{%0,%1,%2,%3}, {%4,%5,%6,%7}, {%8,%9}, {%0,%1,%2,%3};"
        : "+f"(c[0]), "+f"(c[1]), "+f"(c[2]), "+f"(c[3])
        : "r"(a0), "r"(a1), "r"(a2), "r"(a3), "r"(b0), "r"(b1));
}

__device__ __forceinline__ void ldsm_x4(uint32_t& r0, uint32_t& r1,
                                        uint32_t& r2, uint32_t& r3,
                                        uint32_t addr) {
    asm volatile(
        "ldmatrix.sync.aligned.m8n8.x4.shared.b16 {%0,%1,%2,%3}, [%4];"
        : "=r"(r0), "=r"(r1), "=r"(r2), "=r"(r3) : "r"(addr));
}

__device__ __forceinline__ uint32_t smem_u32(const void* p) {
    uint32_t a;
    asm("{ .reg .u64 t; cvta.to.shared.u64 t, %1; cvt.u32.u64 %0, t; }"
        : "=r"(a) : "l"(p));
    return a;
}

// ---------------------------------------------------------------------------
// Main: 128 rows/CTA, 4 warps x (32 x 64), single-product fp16 mma.sync.
// ks=0..2 x loads + bias issued BEFORE the barrier to overlap W staging.
// ---------------------------------------------------------------------------
__global__ __launch_bounds__(NT, 3) void pnn_mma_kernel(
    const float* __restrict__ embeds,   // [N, 64]
    const float* __restrict__ dists,    // [N, 32]
    const float* __restrict__ bias,     // [64]
    float* __restrict__ out,            // [N, 64]
    int N)
{
    __shared__ __half sWh[DN * LD];

    int tid  = threadIdx.x;
    int lane = tid & 31;
    int w    = tid >> 5;
    int g    = lane >> 2;       // 0..7
    int t    = lane & 3;        // 0..3
    int rb   = blockIdx.x * ROWS_PB + w * 32;

    // row indices (q = R*2 + half), clamped for loads
    int rr[4];
#pragma unroll
    for (int q = 0; q < 4; q++) {
        int row = rb + (q >> 1) * 16 + (q & 1) * 8 + g;
        rr[q] = (row < N) ? row : (N - 1);
    }

    // ---- prefetch x for ks=0..2 (pre-barrier: overlap W staging latency) ----
    float4 pre[3][4];
#pragma unroll
    for (int ks = 0; ks < 3; ks++) {
        const float* src = (ks < 2) ? dists : embeds;
        int stride = (ks < 2) ? AN : DN;
        int c0 = ((ks < 2) ? ks * 16 : ks * 16 - AN) + 4 * t;
#pragma unroll
        for (int q = 0; q < 4; q++)
            pre[ks][q] = *(const float4*)(src + (size_t)rr[q] * stride + c0);
    }

    // ---- bias (permuted-N mapping), pre-barrier ----
    float2 bv[8];
#pragma unroll
    for (int G = 0; G < 4; G++) {
        bv[2 * G]     = *(const float2*)(bias + G * 16 + 4 * t);
        bv[2 * G + 1] = *(const float2*)(bias + G * 16 + 4 * t + 2);
    }

    // ---- stage W (768 16B chunks) ----
#pragma unroll
    for (int it = 0; it < 6; it++) {
        int i = tid + it * NT;
        int d = i / 12, kc = i % 12;
        *(uint4*)(sWh + d * LD + kc * 8) = *(const uint4*)(g_Wh + d * KP + kc * 8);
    }
    __syncthreads();

    int nrow = ((lane >> 4) & 1) * 8 + (lane & 7);
    int koff = ((lane >> 3) & 1) * 8;
    uint32_t wh_base = smem_u32(sWh);

    // ---- acc init = bias ----
    float acc[2][8][4];
#pragma unroll
    for (int j = 0; j < 8; j++) {
#pragma unroll
        for (int R = 0; R < 2; R++) {
            acc[R][j][0] = bv[j].x; acc[R][j][1] = bv[j].y;
            acc[R][j][2] = bv[j].x; acc[R][j][3] = bv[j].y;
        }
    }

    // ---- main K loop: 4 LDG.128 (or prefetched) + 4 LDSM -> 16 MMA per ks ----
#pragma unroll
    for (int ks = 0; ks < 6; ks++) {
        float4 xq[4];
        if (ks < 3) {
#pragma unroll
            for (int q = 0; q < 4; q++) xq[q] = pre[ks][q];
        } else {
            int c0 = ks * 16 - AN + 4 * t;   // ks 3..5 are all embeds
#pragma unroll
            for (int q = 0; q < 4; q++)
                xq[q] = *(const float4*)(embeds + (size_t)rr[q] * DN + c0);
        }

        uint32_t ah[2][4];
#pragma unroll
        for (int R = 0; R < 2; R++) {
            float4 p0 = xq[2 * R];
            float4 p1 = xq[2 * R + 1];
            ah[R][0] = cvt_h2(p0.x, p0.y);
            ah[R][1] = cvt_h2(p1.x, p1.y);
            ah[R][2] = cvt_h2(p0.z, p0.w);
            ah[R][3] = cvt_h2(p1.z, p1.w);
        }

#pragma unroll
        for (int t16 = 0; t16 < 4; t16++) {
            uint32_t off = (uint32_t)(((t16 * 16 + nrow) * LD + ks * 16 + koff) * 2);
            uint32_t bh0, bh1, bh2, bh3;
            ldsm_x4(bh0, bh1, bh2, bh3, wh_base + off);
#pragma unroll
            for (int R = 0; R < 2; R++) {
                mma16816(acc[R][2 * t16],     ah[R][0], ah[R][1], ah[R][2], ah[R][3], bh0, bh1);
                mma16816(acc[R][2 * t16 + 1], ah[R][0], ah[R][1], ah[R][2], ah[R][3], bh2, bh3);
            }
        }
    }

    // ---- epilogue: STG.128, logical cols G*16 + 4t + {0..3} ----
#pragma unroll
    for (int R = 0; R < 2; R++) {
        int row0 = rb + R * 16 + g;
        int row1 = row0 + 8;
#pragma unroll
        for (int G = 0; G < 4; G++) {
            if (row0 < N)
                *(float4*)(out + (size_t)row0 * DN + G * 16 + 4 * t) =
                    make_float4(acc[R][2 * G][0], acc[R][2 * G][1],
                                acc[R][2 * G + 1][0], acc[R][2 * G + 1][1]);
            if (row1 < N)
                *(float4*)(out + (size_t)row1 * DN + G * 16 + 4 * t) =
                    make_float4(acc[R][2 * G][2], acc[R][2 * G][3],
                                acc[R][2 * G + 1][2], acc[R][2 * G + 1][3]);
        }
    }
}

// ---------------------------------------------------------------------------
extern "C" void kernel_launch(void* const* d_in, const int* in_sizes, int n_in,
                              void* d_out, int out_size) {
    const float* embeds  = (const float*)d_in[0];
    const float* dists   = (const float*)d_in[1];
    const float* W       = (const float*)d_in[2];
    const float* bias    = (const float*)d_in[3];
    const int*   anchors = (const int*)  d_in[4];

    int N = in_sizes[0] / DN;   // 100000

    prep_kernel<<<24, 256>>>(embeds, W, anchors);

    int blocks = (N + ROWS_PB - 1) / ROWS_PB;   // 782
    pnn_mma_kernel<<<blocks, NT>>>(embeds, dists, bias, (float*)d_out, N);
}